// round 16
// baseline (speedup 1.0000x reference)
#include <cuda_runtime.h>
#include <cstdint>

// ---------------------------------------------------------------------------
// Fixed problem shapes
// ---------------------------------------------------------------------------
static constexpr long long ND = 32768LL * 128;   // 4,194,304
static constexpr int EUP = 524288, EB = 131072;

// ---------------------------------------------------------------------------
// Scratch (__device__ globals; allocation-free rule)
// ---------------------------------------------------------------------------
__device__ float  g_xW [8388608];    // P up (0..ND) and P down (ND..2ND)
__device__ float  g_acc[12582912];
__device__ float  g_z1 [12582912];
__device__ float  g_z2 [12582912];
__device__ float  g_zc [4194304];
__device__ float  g_sums[1792];
__device__ float2 g_aff [896];
__device__ float  g_bb  [256];          // b_up | b_dn contiguous
__device__ int    g_cnt [4];            // last-block counters (stats stages)
__device__ float  g_fragS[4 * 16384];   // tf32 frags: upTop, upBot, dnTop, dnBot
__device__ float  g_fragD[9 * 16384];   // tf32 frags: w1[3], w2[3], comb[3 K-segs]

// ---------------------------------------------------------------------------
// Helpers
// ---------------------------------------------------------------------------
__device__ __forceinline__ unsigned tf32u(float x) {
    unsigned r;
    asm("cvt.rna.tf32.f32 %0, %1;" : "=r"(r) : "f"(x));
    return r;
}
__device__ __forceinline__ float uaf(unsigned u) { return __uint_as_float(u); }
__device__ __forceinline__ unsigned fau(float f) { return __float_as_uint(f); }

__device__ __forceinline__ void mma8(float* d, unsigned a0, unsigned a1,
                                     unsigned a2, unsigned a3,
                                     unsigned b0, unsigned b1) {
    asm volatile(
        "mma.sync.aligned.m16n8k8.row.col.f32.tf32.tf32.f32 "
        "{%0,%1,%2,%3},{%4,%5,%6,%7},{%8,%9},{%0,%1,%2,%3};\n"
        : "+f"(d[0]), "+f"(d[1]), "+f"(d[2]), "+f"(d[3])
        : "r"(a0), "r"(a1), "r"(a2), "r"(a3), "r"(b0), "r"(b1));
}

__device__ __forceinline__ void red4(float* p, float4 v) {
    asm volatile("red.global.add.v4.f32 [%0], {%1,%2,%3,%4};"
                 :: "l"(p), "f"(v.x), "f"(v.y), "f"(v.z), "f"(v.w) : "memory");
}

// Column-permuted fragment slot (validated round 2): each thread's 16
// epilogue outputs are contiguous logical columns [16c, 16c+16).
__device__ __forceinline__ int wfrag_slot(int k, int n) {
    int half = n >> 6, nl = n & 63;
    int t = (nl >> 1) & 7;
    int m = (((nl >> 4) & 3) << 1) | (nl & 1);
    int ln = (m << 2) | (k & 3);
    return (((((k >> 3) << 1) | half) << 3 | t) << 5) | ln;
}

// ---------------------------------------------------------------------------
// init (acc[k]=x, zero sums/counters, pack biases) + W fragment precompute.
//  blocks 0..4095: init copy;  blocks 4096..4108: prep z = bx-4096
// ---------------------------------------------------------------------------
__global__ void __launch_bounds__(256)
k_initprep(const float* __restrict__ x,
           const float* __restrict__ w_up, const float* __restrict__ w_dn,
           const float* __restrict__ w1, const float* __restrict__ w2,
           const float* __restrict__ wcomb,
           const float* __restrict__ b_up, const float* __restrict__ b_dn) {
    int bx = blockIdx.x;
    if (bx < 4096) {
        long long i = (long long)bx * 256 + threadIdx.x;
        float4 v = ((const float4*)x)[i];
        ((float4*)g_acc)[i]           = v;
        ((float4*)g_acc)[i + 1048576] = v;
        ((float4*)g_acc)[i + 2097152] = v;
        if (bx == 0) {
            for (int j = threadIdx.x; j < 1792; j += 256) g_sums[j] = 0.f;
            int t = threadIdx.x;
            if (t < 128) {
                g_bb[t]       = b_up[t];
                g_bb[128 + t] = b_dn[t];
            }
            if (t < 4) g_cnt[t] = 0;
        }
        return;
    }
    int z = bx - 4096;
    const float* Wz;
    if (z < 4)       Wz = (z < 2 ? w_up : w_dn) + (z & 1) * 16384;
    else if (z < 7)  Wz = w1 + (z - 4) * 16384;
    else if (z < 10) Wz = w2 + (z - 7) * 16384;
    else             Wz = wcomb + (z - 10) * 16384;
    float* Fz = (z < 4) ? (g_fragS + z * 16384) : (g_fragD + (z - 4) * 16384);

    for (int i = threadIdx.x; i < 4096; i += 256) {
        int k = i >> 5, n4 = (i & 31) << 2;
        float4 w = *(const float4*)(Wz + k * 128 + n4);
        float wv[4] = {w.x, w.y, w.z, w.w};
        int jb = (k >> 2) & 1;
#pragma unroll
        for (int j = 0; j < 4; j++)
            Fz[wfrag_slot(k, n4 + j) * 2 + jb] = uaf(tf32u(wv[j]));
    }
}

// ---------------------------------------------------------------------------
// Edge GEMM + gather-add-relu-scatter (up & down merged via blockIdx.z).
// 128-edge x 128-col tile; warp M=32 (2 x m16); B (float2) loaded once per t
// and reused for both m-subtiles.  Proven best version — UNCHANGED.
// ---------------------------------------------------------------------------
__global__ void __launch_bounds__(256, 2)
k_edge(const float* __restrict__ attrU, const float* __restrict__ attrD,
       const float* __restrict__ FwU, const float* __restrict__ FwD,
       const float* __restrict__ Pbase, const int* __restrict__ idxU,
       const int* __restrict__ idxD, float* __restrict__ outbase, int E) {
    extern __shared__ float As[];   // 128 x 132
    int z = blockIdx.z;
    const float* attr = z ? attrD : attrU;
    const float* Fw   = z ? FwD   : FwU;
    const int*   idx  = z ? idxD  : idxU;
    const float* P    = Pbase   + (long long)z * ND;
    float*       outp = outbase + (long long)z * ND;

    int tid = threadIdx.x, lane = tid & 31, wrp = tid >> 5;
    int wr = wrp >> 1, wc = wrp & 1;
    int ebase = blockIdx.x << 7;

    for (int i = tid; i < 4096; i += 256) {
        int r = i >> 5, c4 = (i & 31) << 2;
        float4 a = __ldcs((const float4*)(attr + (long long)(ebase + r) * 128 + c4));
        float4 s = make_float4(uaf(tf32u(a.x)), uaf(tf32u(a.y)),
                               uaf(tf32u(a.z)), uaf(tf32u(a.w)));
        *(float4*)(As + r * 132 + c4) = s;
    }
    __syncthreads();

    float acc[2][8][4];
#pragma unroll
    for (int m = 0; m < 2; m++)
#pragma unroll
        for (int t = 0; t < 8; t++)
#pragma unroll
            for (int j = 0; j < 4; j++) acc[m][t][j] = 0.f;

    int arow = (wr << 5) + (lane >> 2);
    int acol = lane & 3;
    const float2* FB = (const float2*)Fw;

#pragma unroll
    for (int ks = 0; ks < 16; ks++) {
        int k0 = ks << 3;
        unsigned a0 = fau(As[arow * 132 + k0 + acol]);
        unsigned a1 = fau(As[(arow + 8) * 132 + k0 + acol]);
        unsigned a2 = fau(As[arow * 132 + k0 + acol + 4]);
        unsigned a3 = fau(As[(arow + 8) * 132 + k0 + acol + 4]);
        unsigned c0 = fau(As[(arow + 16) * 132 + k0 + acol]);
        unsigned c1 = fau(As[(arow + 24) * 132 + k0 + acol]);
        unsigned c2 = fau(As[(arow + 16) * 132 + k0 + acol + 4]);
        unsigned c3 = fau(As[(arow + 24) * 132 + k0 + acol + 4]);
        const float2* bp = FB + (((ks << 1) | wc) << 8) + lane;
#pragma unroll
        for (int t = 0; t < 8; t++) {
            float2 b = __ldg(bp + (t << 5));
            unsigned b0 = fau(b.x), b1 = fau(b.y);
            mma8(acc[0][t], a0, a1, a2, a3, b0, b1);
            mma8(acc[1][t], c0, c1, c2, c3, b0, b1);
        }
    }

    // epilogue: + P[src], relu, red-add to out[dst]
    int cg = lane & 3;
    int colbase = (wc << 6) + (cg << 4);
#pragma unroll
    for (int m = 0; m < 2; m++)
#pragma unroll
        for (int rr = 0; rr < 2; rr++) {
            int e = ebase + (wr << 5) + (m << 4) + (lane >> 2) + (rr << 3);
            int dst = idx[e];
            int src = idx[E + e];
            const float4* pp = (const float4*)(P + (long long)src * 128 + colbase);
            float* op = outp + (long long)dst * 128 + colbase;
#pragma unroll
            for (int q = 0; q < 4; q++) {
                float4 pv = __ldcg(pp + q);
                float4 v;
                v.x = fmaxf(acc[m][2 * q][rr * 2 + 0] + pv.x, 0.f);
                v.y = fmaxf(acc[m][2 * q][rr * 2 + 1] + pv.y, 0.f);
                v.z = fmaxf(acc[m][2 * q + 1][rr * 2 + 0] + pv.z, 0.f);
                v.w = fmaxf(acc[m][2 * q + 1][rr * 2 + 1] + pv.w, 0.f);
                red4(op + (q << 2), v);
            }
        }
}

// ---------------------------------------------------------------------------
// Node GEMM, single tf32 (round-15 proven, 3 CTAs/SM — UNCHANGED).
// ---------------------------------------------------------------------------
__global__ void __launch_bounds__(256, 3)
k_node(const float* __restrict__ A, long long aZ, long long segStride,
       const float* __restrict__ Fw, long long fZ,
       const float* __restrict__ bias, int bZ,
       const float2* __restrict__ affine, int affZ,
       float* __restrict__ C, long long cZ, int K) {
    extern __shared__ float As1[];   // 64 x 68 float

    int z = blockIdx.z;
    int tid = threadIdx.x, lane = tid & 31, wrp = tid >> 5;
    int wr = wrp >> 1, wc = wrp & 1;
    int row0 = blockIdx.x << 6;

    const float*  Az   = A + (long long)z * aZ;
    const float*  Fz   = Fw + (long long)z * fZ;
    const float2* affz = affine ? (affine + (long long)z * affZ) : (const float2*)0;

    int arow = (wr << 4) + (lane >> 2);
    int acol = lane & 3;

    float acc[8][4];
#pragma unroll
    for (int t = 0; t < 8; t++)
#pragma unroll
        for (int j = 0; j < 4; j++) acc[t][j] = 0.f;

    for (int kc = 0; kc < K; kc += 64) {
        __syncthreads();
        {
            int seg = kc >> 7, kin = kc & 127;
            for (int i = tid; i < 1024; i += 256) {
                int r = i >> 4, c4 = (i & 15) << 2;
                float4 a = *(const float4*)(Az + (long long)seg * segStride +
                                            (long long)(row0 + r) * 128 + kin + c4);
                float av[4] = {a.x, a.y, a.z, a.w};
#pragma unroll
                for (int j = 0; j < 4; j++) {
                    float v = av[j];
                    if (affz) {
                        float2 sc = affz[kc + c4 + j];
                        v = fmaxf(fmaf(v, sc.x, sc.y), 0.f);
                    }
                    As1[r * 68 + c4 + j] = uaf(tf32u(v));
                }
            }
        }
        __syncthreads();

        int khalf8 = ((kc >> 6) & 1) << 3;
        const float2* FB = (const float2*)Fz + (kc >> 7) * 8192;  // per-K128-seg frags
#pragma unroll
        for (int ks = 0; ks < 8; ks++) {
            int ksp = khalf8 | ks;
            int k0 = ks << 3;
            int bb = ((((ksp << 1) | wc) << 3) << 5) + lane;
            unsigned a0 = fau(As1[arow * 68 + k0 + acol]);
            unsigned a1 = fau(As1[(arow + 8) * 68 + k0 + acol]);
            unsigned a2 = fau(As1[arow * 68 + k0 + acol + 4]);
            unsigned a3 = fau(As1[(arow + 8) * 68 + k0 + acol + 4]);
#pragma unroll
            for (int t = 0; t < 8; t++) {
                float2 b = __ldg(FB + bb + (t << 5));
                mma8(acc[t], a0, a1, a2, a3, fau(b.x), fau(b.y));
            }
        }
    }

    // epilogue: C = acc + bias
    int cg = lane & 3;
    int colbase = (wc << 6) + (cg << 4);
    const float* bp = bias + (long long)z * bZ + colbase;
    float4 bv[4] = {*(const float4*)(bp),     *(const float4*)(bp + 4),
                    *(const float4*)(bp + 8), *(const float4*)(bp + 12)};
    float* Cz = C + (long long)z * cZ;
#pragma unroll
    for (int rr = 0; rr < 2; rr++) {
        int rg = row0 + (wr << 4) + (lane >> 2) + (rr << 3);
        float* cp = Cz + (long long)rg * 128 + colbase;
#pragma unroll
        for (int q = 0; q < 4; q++) {
            float4 v;
            v.x = acc[2 * q][rr * 2 + 0] + bv[q].x;
            v.y = acc[2 * q][rr * 2 + 1] + bv[q].y;
            v.z = acc[2 * q + 1][rr * 2 + 0] + bv[q].z;
            v.w = acc[2 * q + 1][rr * 2 + 1] + bv[q].w;
            *(float4*)(cp + (q << 2)) = v;
        }
    }
}

// ---------------------------------------------------------------------------
// Boundary scatter: out[dst] += boundary_attr[gidx]
// ---------------------------------------------------------------------------
__global__ void __launch_bounds__(256)
k_boundary(const float* __restrict__ battr, const int* __restrict__ idx,
           float* __restrict__ outp, int E) {
    int t = blockIdx.x * 256 + threadIdx.x;
    int e = t >> 5, q = t & 31;
    int gi = idx[e];
    int dst = idx[E + e];
    float4 v = __ldcg((const float4*)(battr + (long long)gi * 128 + (q << 2)));
    red4(outp + (long long)dst * 128 + (q << 2), v);
}

// ---------------------------------------------------------------------------
// BN column stats + LAST-BLOCK finalize (merges k_fin; round 16).
// 128 rows per block.  After accumulation, the last block to finish computes
// all (scale, shift) pairs — deterministic, graph-capturable.
// ---------------------------------------------------------------------------
__global__ void __launch_bounds__(128)
k_stats(const float* __restrict__ A, long long zStride, float* __restrict__ sums,
        const float* __restrict__ g, const float* __restrict__ be,
        float2* __restrict__ aff, int* __restrict__ cnt) {
    const float* p = A + (long long)blockIdx.z * zStride +
                     (long long)blockIdx.x * 128 * 128 + threadIdx.x;
    float s = 0.f, q = 0.f;
#pragma unroll 8
    for (int r = 0; r < 128; r++) {
        float v = p[(long long)r * 128];
        s += v;
        q += v * v;
    }
    atomicAdd(&sums[blockIdx.z * 256 + threadIdx.x], s);
    atomicAdd(&sums[blockIdx.z * 256 + 128 + threadIdx.x], q);

    __threadfence();
    __shared__ int isLast;
    if (threadIdx.x == 0) {
        int total = gridDim.x * gridDim.z;
        isLast = (atomicAdd(cnt, 1) == total - 1) ? 1 : 0;
    }
    __syncthreads();
    if (isLast) {
        int n = gridDim.z * 128;
        for (int i = threadIdx.x; i < n; i += 128) {
            int zz = i >> 7, col = i & 127;
            float sv = sums[zz * 256 + col], qq = sums[zz * 256 + 128 + col];
            float mean = sv * (1.f / 32768.f);
            float var = qq * (1.f / 32768.f) - mean * mean;
            float sc = g[i] * rsqrtf(var + 1e-5f);
            aff[i] = make_float2(sc, fmaf(-mean, sc, be[i]));
        }
    }
}

// ---------------------------------------------------------------------------
// Final: out = relu(bn(zc))
// ---------------------------------------------------------------------------
__global__ void __launch_bounds__(256) k_out(float* __restrict__ outp) {
    long long i = (long long)blockIdx.x * 256 + threadIdx.x;
    float4 v = ((const float4*)g_zc)[i];
    int col = (int)((i & 31) << 2);
    const float2* a = g_aff + 768 + col;
    float4 o;
    o.x = fmaxf(fmaf(v.x, a[0].x, a[0].y), 0.f);
    o.y = fmaxf(fmaf(v.y, a[1].x, a[1].y), 0.f);
    o.z = fmaxf(fmaf(v.z, a[2].x, a[2].y), 0.f);
    o.w = fmaxf(fmaf(v.w, a[3].x, a[3].y), 0.f);
    ((float4*)outp)[i] = o;
}

// ---------------------------------------------------------------------------
// kernel_launch
// ---------------------------------------------------------------------------
extern "C" void kernel_launch(void* const* d_in, const int* in_sizes, int n_in,
                              void* d_out, int out_size) {
    (void)in_sizes; (void)n_in; (void)out_size;

    const float* x       = (const float*)d_in[0];
    const int*   up_idx  = (const int*)d_in[1];
    const int*   dn_idx  = (const int*)d_in[2];
    const int*   b_idx   = (const int*)d_in[3];
    const float* up_attr = (const float*)d_in[4];
    const float* dn_attr = (const float*)d_in[5];
    const float* b_attr  = (const float*)d_in[6];
    const float* w_up    = (const float*)d_in[7];
    const float* b_up    = (const float*)d_in[8];
    const float* w_dn    = (const float*)d_in[9];
    const float* b_dn    = (const float*)d_in[10];
    const float* w1      = (const float*)d_in[11];
    const float* bb1     = (const float*)d_in[12];
    const float* g1      = (const float*)d_in[13];
    const float* be1     = (const float*)d_in[14];
    const float* w2      = (const float*)d_in[15];
    const float* bb2     = (const float*)d_in[16];
    const float* g2      = (const float*)d_in[17];
    const float* be2     = (const float*)d_in[18];
    const float* wcomb   = (const float*)d_in[19];
    const float* bcomb   = (const float*)d_in[20];
    const float* gcomb   = (const float*)d_in[21];
    const float* becomb  = (const float*)d_in[22];
    float* out = (float*)d_out;

    void *p0, *p2, *p3, *p4, *p5, *p6, *p7, *p8, *p9, *pb, *pc;
    cudaGetSymbolAddress(&p0, g_xW);
    cudaGetSymbolAddress(&p2, g_acc);
    cudaGetSymbolAddress(&p3, g_z1);
    cudaGetSymbolAddress(&p4, g_z2);
    cudaGetSymbolAddress(&p5, g_zc);
    cudaGetSymbolAddress(&p6, g_sums);
    cudaGetSymbolAddress(&p7, g_aff);
    cudaGetSymbolAddress(&p8, g_fragS);
    cudaGetSymbolAddress(&p9, g_fragD);
    cudaGetSymbolAddress(&pb, g_bb);
    cudaGetSymbolAddress(&pc, g_cnt);
    float*  xW    = (float*)p0;
    float*  acc   = (float*)p2;
    float*  z1    = (float*)p3;
    float*  z2    = (float*)p4;
    float*  zc    = (float*)p5;
    float*  sums  = (float*)p6;
    float2* aff   = (float2*)p7;
    float*  fragS = (float*)p8;
    float*  fragD = (float*)p9;
    float*  bb    = (float*)pb;
    int*    cnt   = (int*)pc;

    const int ESM  = 128 * 132 * 4;   // 67584
    const int NSM1 = 64 * 68 * 4;     // 17408
    cudaFuncSetAttribute(k_edge, cudaFuncAttributeMaxDynamicSharedMemorySize, ESM);
    cudaFuncSetAttribute(k_node, cudaFuncAttributeMaxDynamicSharedMemorySize, NSM1);

    // 0: init + fragment precompute + bias pack + counter reset (one launch)
    k_initprep<<<4109, 256>>>(x, w_up, w_dn, w1, w2, wcomb, b_up, b_dn);

    // 1: boundary scatter
    k_boundary<<<16384, 256>>>(b_attr, b_idx, acc + 2 * ND, EB);

    // 2: P[z] = x @ W_top[z] + b[z], z in {up, dn}; fZ=32768 (skip Bot frags)
    k_node<<<dim3(512, 1, 2), 256, NSM1>>>(
        x, 0, 0, fragS, 32768, bb, 128, (const float2*)0, 0, xW, ND, 128);

    // 3: edge GEMM + scatter, up & dn merged
    k_edge<<<dim3(4096, 1, 2), 256, ESM>>>(up_attr, dn_attr,
                                           fragS + 16384, fragS + 49152,
                                           xW, up_idx, dn_idx, acc, EUP);

    // 4: z1 = h @ w1 + b1 ; stats+fin fused (last-block finalize)
    k_node<<<dim3(512, 1, 3), 256, NSM1>>>(
        acc, ND, 0, fragD, 16384, bb1, 128, (const float2*)0, 0, z1, ND, 128);
    k_stats<<<dim3(256, 1, 3), 128>>>(z1, ND, sums, g1, be1, aff, cnt);

    // 5: z2 = relu(bn(z1)) @ w2 + b2
    k_node<<<dim3(512, 1, 3), 256, NSM1>>>(
        z1, ND, 0, fragD + 3 * 16384, 16384, bb2, 128, aff, 128, z2, ND, 128);
    k_stats<<<dim3(256, 1, 3), 128>>>(z2, ND, sums + 768, g2, be2, aff + 384,
                                      cnt + 1);

    // 6: zc = cat(relu(bn(z2))) @ comb_w + comb_b (K=384, 3 frag segments)
    k_node<<<dim3(512, 1, 1), 256, NSM1>>>(
        z2, 0, ND, fragD + 6 * 16384, 0, bcomb, 0, aff + 384, 0, zc, 0, 384);
    k_stats<<<dim3(256, 1, 1), 128>>>(zc, 0, sums + 1536, gcomb, becomb,
                                      aff + 768, cnt + 2);

    // 7: out = relu(bn(zc))
    k_out<<<4096, 256>>>(out);
}

// round 17
// speedup vs baseline: 1.0026x; 1.0026x over previous
#include <cuda_runtime.h>
#include <cstdint>

// ---------------------------------------------------------------------------
// Fixed problem shapes
// ---------------------------------------------------------------------------
static constexpr long long ND = 32768LL * 128;   // 4,194,304
static constexpr int EUP = 524288, EB = 131072;

// ---------------------------------------------------------------------------
// Scratch (__device__ globals; allocation-free rule)
// ---------------------------------------------------------------------------
__device__ float  g_xW [8388608];    // P up (0..ND) and P down (ND..2ND)
__device__ float  g_acc[12582912];
__device__ float  g_z1 [12582912];
__device__ float  g_z2 [12582912];
__device__ float  g_zc [4194304];
__device__ float  g_sums[1792];
__device__ float2 g_aff [896];
__device__ float  g_bb  [256];          // b_up | b_dn contiguous
__device__ float  g_fragS[4 * 16384];   // tf32 frags: upTop, upBot, dnTop, dnBot
__device__ float  g_fragD[9 * 16384];   // tf32 frags: w1[3], w2[3], comb[3 K-segs]

// ---------------------------------------------------------------------------
// Helpers
// ---------------------------------------------------------------------------
__device__ __forceinline__ unsigned tf32u(float x) {
    unsigned r;
    asm("cvt.rna.tf32.f32 %0, %1;" : "=r"(r) : "f"(x));
    return r;
}
__device__ __forceinline__ float uaf(unsigned u) { return __uint_as_float(u); }
__device__ __forceinline__ unsigned fau(float f) { return __float_as_uint(f); }

__device__ __forceinline__ void mma8(float* d, unsigned a0, unsigned a1,
                                     unsigned a2, unsigned a3,
                                     unsigned b0, unsigned b1) {
    asm volatile(
        "mma.sync.aligned.m16n8k8.row.col.f32.tf32.tf32.f32 "
        "{%0,%1,%2,%3},{%4,%5,%6,%7},{%8,%9},{%0,%1,%2,%3};\n"
        : "+f"(d[0]), "+f"(d[1]), "+f"(d[2]), "+f"(d[3])
        : "r"(a0), "r"(a1), "r"(a2), "r"(a3), "r"(b0), "r"(b1));
}

__device__ __forceinline__ void red4(float* p, float4 v) {
    asm volatile("red.global.add.v4.f32 [%0], {%1,%2,%3,%4};"
                 :: "l"(p), "f"(v.x), "f"(v.y), "f"(v.z), "f"(v.w) : "memory");
}

// Column-permuted fragment slot (validated round 2): each thread's 16
// epilogue outputs are contiguous logical columns [16c, 16c+16).
__device__ __forceinline__ int wfrag_slot(int k, int n) {
    int half = n >> 6, nl = n & 63;
    int t = (nl >> 1) & 7;
    int m = (((nl >> 4) & 3) << 1) | (nl & 1);
    int ln = (m << 2) | (k & 3);
    return (((((k >> 3) << 1) | half) << 3 | t) << 5) | ln;
}

// ---------------------------------------------------------------------------
// init (acc[k]=x, zero sums, pack biases) + W fragment precompute, ONE launch.
//  blocks 0..4095: init copy;  blocks 4096..4108: prep z = bx-4096
// ---------------------------------------------------------------------------
__global__ void __launch_bounds__(256)
k_initprep(const float* __restrict__ x,
           const float* __restrict__ w_up, const float* __restrict__ w_dn,
           const float* __restrict__ w1, const float* __restrict__ w2,
           const float* __restrict__ wcomb,
           const float* __restrict__ b_up, const float* __restrict__ b_dn) {
    int bx = blockIdx.x;
    if (bx < 4096) {
        long long i = (long long)bx * 256 + threadIdx.x;
        float4 v = ((const float4*)x)[i];
        ((float4*)g_acc)[i]           = v;
        ((float4*)g_acc)[i + 1048576] = v;
        ((float4*)g_acc)[i + 2097152] = v;
        if (bx == 0) {
            for (int j = threadIdx.x; j < 1792; j += 256) g_sums[j] = 0.f;
            int t = threadIdx.x;
            if (t < 128) {
                g_bb[t]       = b_up[t];
                g_bb[128 + t] = b_dn[t];
            }
        }
        return;
    }
    int z = bx - 4096;
    const float* Wz;
    if (z < 4)       Wz = (z < 2 ? w_up : w_dn) + (z & 1) * 16384;
    else if (z < 7)  Wz = w1 + (z - 4) * 16384;
    else if (z < 10) Wz = w2 + (z - 7) * 16384;
    else             Wz = wcomb + (z - 10) * 16384;
    float* Fz = (z < 4) ? (g_fragS + z * 16384) : (g_fragD + (z - 4) * 16384);

    for (int i = threadIdx.x; i < 4096; i += 256) {
        int k = i >> 5, n4 = (i & 31) << 2;
        float4 w = *(const float4*)(Wz + k * 128 + n4);
        float wv[4] = {w.x, w.y, w.z, w.w};
        int jb = (k >> 2) & 1;
#pragma unroll
        for (int j = 0; j < 4; j++)
            Fz[wfrag_slot(k, n4 + j) * 2 + jb] = uaf(tf32u(wv[j]));
    }
}

// ---------------------------------------------------------------------------
// Edge GEMM + gather-add-relu-scatter (up & down merged via blockIdx.z).
// 128-edge x 128-col tile; warp M=32 (2 x m16); B (float2) loaded once per t
// and reused for both m-subtiles.  Proven best version — UNCHANGED.
// ---------------------------------------------------------------------------
__global__ void __launch_bounds__(256, 2)
k_edge(const float* __restrict__ attrU, const float* __restrict__ attrD,
       const float* __restrict__ FwU, const float* __restrict__ FwD,
       const float* __restrict__ Pbase, const int* __restrict__ idxU,
       const int* __restrict__ idxD, float* __restrict__ outbase, int E) {
    extern __shared__ float As[];   // 128 x 132
    int z = blockIdx.z;
    const float* attr = z ? attrD : attrU;
    const float* Fw   = z ? FwD   : FwU;
    const int*   idx  = z ? idxD  : idxU;
    const float* P    = Pbase   + (long long)z * ND;
    float*       outp = outbase + (long long)z * ND;

    int tid = threadIdx.x, lane = tid & 31, wrp = tid >> 5;
    int wr = wrp >> 1, wc = wrp & 1;
    int ebase = blockIdx.x << 7;

    for (int i = tid; i < 4096; i += 256) {
        int r = i >> 5, c4 = (i & 31) << 2;
        float4 a = __ldcs((const float4*)(attr + (long long)(ebase + r) * 128 + c4));
        float4 s = make_float4(uaf(tf32u(a.x)), uaf(tf32u(a.y)),
                               uaf(tf32u(a.z)), uaf(tf32u(a.w)));
        *(float4*)(As + r * 132 + c4) = s;
    }
    __syncthreads();

    float acc[2][8][4];
#pragma unroll
    for (int m = 0; m < 2; m++)
#pragma unroll
        for (int t = 0; t < 8; t++)
#pragma unroll
            for (int j = 0; j < 4; j++) acc[m][t][j] = 0.f;

    int arow = (wr << 5) + (lane >> 2);
    int acol = lane & 3;
    const float2* FB = (const float2*)Fw;

#pragma unroll
    for (int ks = 0; ks < 16; ks++) {
        int k0 = ks << 3;
        unsigned a0 = fau(As[arow * 132 + k0 + acol]);
        unsigned a1 = fau(As[(arow + 8) * 132 + k0 + acol]);
        unsigned a2 = fau(As[arow * 132 + k0 + acol + 4]);
        unsigned a3 = fau(As[(arow + 8) * 132 + k0 + acol + 4]);
        unsigned c0 = fau(As[(arow + 16) * 132 + k0 + acol]);
        unsigned c1 = fau(As[(arow + 24) * 132 + k0 + acol]);
        unsigned c2 = fau(As[(arow + 16) * 132 + k0 + acol + 4]);
        unsigned c3 = fau(As[(arow + 24) * 132 + k0 + acol + 4]);
        const float2* bp = FB + (((ks << 1) | wc) << 8) + lane;
#pragma unroll
        for (int t = 0; t < 8; t++) {
            float2 b = __ldg(bp + (t << 5));
            unsigned b0 = fau(b.x), b1 = fau(b.y);
            mma8(acc[0][t], a0, a1, a2, a3, b0, b1);
            mma8(acc[1][t], c0, c1, c2, c3, b0, b1);
        }
    }

    // epilogue: + P[src], relu, red-add to out[dst]
    int cg = lane & 3;
    int colbase = (wc << 6) + (cg << 4);
#pragma unroll
    for (int m = 0; m < 2; m++)
#pragma unroll
        for (int rr = 0; rr < 2; rr++) {
            int e = ebase + (wr << 5) + (m << 4) + (lane >> 2) + (rr << 3);
            int dst = idx[e];
            int src = idx[E + e];
            const float4* pp = (const float4*)(P + (long long)src * 128 + colbase);
            float* op = outp + (long long)dst * 128 + colbase;
#pragma unroll
            for (int q = 0; q < 4; q++) {
                float4 pv = __ldcg(pp + q);
                float4 v;
                v.x = fmaxf(acc[m][2 * q][rr * 2 + 0] + pv.x, 0.f);
                v.y = fmaxf(acc[m][2 * q][rr * 2 + 1] + pv.y, 0.f);
                v.z = fmaxf(acc[m][2 * q + 1][rr * 2 + 0] + pv.z, 0.f);
                v.w = fmaxf(acc[m][2 * q + 1][rr * 2 + 1] + pv.w, 0.f);
                red4(op + (q << 2), v);
            }
        }
}

// ---------------------------------------------------------------------------
// Node GEMM, single tf32: C = op(A) @ W + bias; op = relu(bn affine) if
// affine != null.  64-row tile, warp M=16; B frags from global; K in {128,384}.
// 3 CTAs/SM (85-reg cap; mainloop live set ~60 regs, no spill).
// ---------------------------------------------------------------------------
__global__ void __launch_bounds__(256, 3)
k_node(const float* __restrict__ A, long long aZ, long long segStride,
       const float* __restrict__ Fw, long long fZ,
       const float* __restrict__ bias, int bZ,
       const float2* __restrict__ affine, int affZ,
       float* __restrict__ C, long long cZ, int K) {
    extern __shared__ float As1[];   // 64 x 68 float

    int z = blockIdx.z;
    int tid = threadIdx.x, lane = tid & 31, wrp = tid >> 5;
    int wr = wrp >> 1, wc = wrp & 1;
    int row0 = blockIdx.x << 6;

    const float*  Az   = A + (long long)z * aZ;
    const float*  Fz   = Fw + (long long)z * fZ;
    const float2* affz = affine ? (affine + (long long)z * affZ) : (const float2*)0;

    int arow = (wr << 4) + (lane >> 2);
    int acol = lane & 3;

    float acc[8][4];
#pragma unroll
    for (int t = 0; t < 8; t++)
#pragma unroll
        for (int j = 0; j < 4; j++) acc[t][j] = 0.f;

    for (int kc = 0; kc < K; kc += 64) {
        __syncthreads();
        {
            int seg = kc >> 7, kin = kc & 127;
            for (int i = tid; i < 1024; i += 256) {
                int r = i >> 4, c4 = (i & 15) << 2;
                float4 a = *(const float4*)(Az + (long long)seg * segStride +
                                            (long long)(row0 + r) * 128 + kin + c4);
                float av[4] = {a.x, a.y, a.z, a.w};
#pragma unroll
                for (int j = 0; j < 4; j++) {
                    float v = av[j];
                    if (affz) {
                        float2 sc = affz[kc + c4 + j];
                        v = fmaxf(fmaf(v, sc.x, sc.y), 0.f);
                    }
                    As1[r * 68 + c4 + j] = uaf(tf32u(v));
                }
            }
        }
        __syncthreads();

        int khalf8 = ((kc >> 6) & 1) << 3;
        const float2* FB = (const float2*)Fz + (kc >> 7) * 8192;  // per-K128-seg frags
#pragma unroll
        for (int ks = 0; ks < 8; ks++) {
            int ksp = khalf8 | ks;
            int k0 = ks << 3;
            int bb = ((((ksp << 1) | wc) << 3) << 5) + lane;
            unsigned a0 = fau(As1[arow * 68 + k0 + acol]);
            unsigned a1 = fau(As1[(arow + 8) * 68 + k0 + acol]);
            unsigned a2 = fau(As1[arow * 68 + k0 + acol + 4]);
            unsigned a3 = fau(As1[(arow + 8) * 68 + k0 + acol + 4]);
#pragma unroll
            for (int t = 0; t < 8; t++) {
                float2 b = __ldg(FB + bb + (t << 5));
                mma8(acc[t], a0, a1, a2, a3, fau(b.x), fau(b.y));
            }
        }
    }

    // epilogue: C = acc + bias
    int cg = lane & 3;
    int colbase = (wc << 6) + (cg << 4);
    const float* bp = bias + (long long)z * bZ + colbase;
    float4 bv[4] = {*(const float4*)(bp),     *(const float4*)(bp + 4),
                    *(const float4*)(bp + 8), *(const float4*)(bp + 12)};
    float* Cz = C + (long long)z * cZ;
#pragma unroll
    for (int rr = 0; rr < 2; rr++) {
        int rg = row0 + (wr << 4) + (lane >> 2) + (rr << 3);
        float* cp = Cz + (long long)rg * 128 + colbase;
#pragma unroll
        for (int q = 0; q < 4; q++) {
            float4 v;
            v.x = acc[2 * q][rr * 2 + 0] + bv[q].x;
            v.y = acc[2 * q][rr * 2 + 1] + bv[q].y;
            v.z = acc[2 * q + 1][rr * 2 + 0] + bv[q].z;
            v.w = acc[2 * q + 1][rr * 2 + 1] + bv[q].w;
            *(float4*)(cp + (q << 2)) = v;
        }
    }
}

// ---------------------------------------------------------------------------
// Boundary scatter: out[dst] += boundary_attr[gidx]
// ---------------------------------------------------------------------------
__global__ void __launch_bounds__(256)
k_boundary(const float* __restrict__ battr, const int* __restrict__ idx,
           float* __restrict__ outp, int E) {
    int t = blockIdx.x * 256 + threadIdx.x;
    int e = t >> 5, q = t & 31;
    int gi = idx[e];
    int dst = idx[E + e];
    float4 v = __ldcg((const float4*)(battr + (long long)gi * 128 + (q << 2)));
    red4(outp + (long long)dst * 128 + (q << 2), v);
}

// ---------------------------------------------------------------------------
// BN column stats (separate pass — proven).  128 rows per block.
// ---------------------------------------------------------------------------
__global__ void __launch_bounds__(128)
k_stats(const float* __restrict__ A, long long zStride, float* __restrict__ sums) {
    const float* p = A + (long long)blockIdx.z * zStride +
                     (long long)blockIdx.x * 128 * 128 + threadIdx.x;
    float s = 0.f, q = 0.f;
#pragma unroll 8
    for (int r = 0; r < 128; r++) {
        float v = p[(long long)r * 128];
        s += v;
        q += v * v;
    }
    atomicAdd(&sums[blockIdx.z * 256 + threadIdx.x], s);
    atomicAdd(&sums[blockIdx.z * 256 + 128 + threadIdx.x], q);
}

__global__ void k_fin(const float* __restrict__ sums, const float* __restrict__ g,
                      const float* __restrict__ be, float2* __restrict__ aff, int n) {
    int i = blockIdx.x * 128 + threadIdx.x;
    if (i < n) {
        int zz = i >> 7, col = i & 127;
        float sv = sums[zz * 256 + col], qq = sums[zz * 256 + 128 + col];
        float mean = sv * (1.f / 32768.f);
        float var = qq * (1.f / 32768.f) - mean * mean;
        float sc = g[i] * rsqrtf(var + 1e-5f);
        aff[i] = make_float2(sc, fmaf(-mean, sc, be[i]));
    }
}

// ---------------------------------------------------------------------------
// Final: out = relu(bn(zc))
// ---------------------------------------------------------------------------
__global__ void __launch_bounds__(256) k_out(float* __restrict__ outp) {
    long long i = (long long)blockIdx.x * 256 + threadIdx.x;
    float4 v = ((const float4*)g_zc)[i];
    int col = (int)((i & 31) << 2);
    const float2* a = g_aff + 768 + col;
    float4 o;
    o.x = fmaxf(fmaf(v.x, a[0].x, a[0].y), 0.f);
    o.y = fmaxf(fmaf(v.y, a[1].x, a[1].y), 0.f);
    o.z = fmaxf(fmaf(v.z, a[2].x, a[2].y), 0.f);
    o.w = fmaxf(fmaf(v.w, a[3].x, a[3].y), 0.f);
    ((float4*)outp)[i] = o;
}

// ---------------------------------------------------------------------------
// kernel_launch
// ---------------------------------------------------------------------------
extern "C" void kernel_launch(void* const* d_in, const int* in_sizes, int n_in,
                              void* d_out, int out_size) {
    (void)in_sizes; (void)n_in; (void)out_size;

    const float* x       = (const float*)d_in[0];
    const int*   up_idx  = (const int*)d_in[1];
    const int*   dn_idx  = (const int*)d_in[2];
    const int*   b_idx   = (const int*)d_in[3];
    const float* up_attr = (const float*)d_in[4];
    const float* dn_attr = (const float*)d_in[5];
    const float* b_attr  = (const float*)d_in[6];
    const float* w_up    = (const float*)d_in[7];
    const float* b_up    = (const float*)d_in[8];
    const float* w_dn    = (const float*)d_in[9];
    const float* b_dn    = (const float*)d_in[10];
    const float* w1      = (const float*)d_in[11];
    const float* bb1     = (const float*)d_in[12];
    const float* g1      = (const float*)d_in[13];
    const float* be1     = (const float*)d_in[14];
    const float* w2      = (const float*)d_in[15];
    const float* bb2     = (const float*)d_in[16];
    const float* g2      = (const float*)d_in[17];
    const float* be2     = (const float*)d_in[18];
    const float* wcomb   = (const float*)d_in[19];
    const float* bcomb   = (const float*)d_in[20];
    const float* gcomb   = (const float*)d_in[21];
    const float* becomb  = (const float*)d_in[22];
    float* out = (float*)d_out;

    void *p0, *p2, *p3, *p4, *p5, *p6, *p7, *p8, *p9, *pb;
    cudaGetSymbolAddress(&p0, g_xW);
    cudaGetSymbolAddress(&p2, g_acc);
    cudaGetSymbolAddress(&p3, g_z1);
    cudaGetSymbolAddress(&p4, g_z2);
    cudaGetSymbolAddress(&p5, g_zc);
    cudaGetSymbolAddress(&p6, g_sums);
    cudaGetSymbolAddress(&p7, g_aff);
    cudaGetSymbolAddress(&p8, g_fragS);
    cudaGetSymbolAddress(&p9, g_fragD);
    cudaGetSymbolAddress(&pb, g_bb);
    float*  xW    = (float*)p0;
    float*  acc   = (float*)p2;
    float*  z1    = (float*)p3;
    float*  z2    = (float*)p4;
    float*  zc    = (float*)p5;
    float*  sums  = (float*)p6;
    float2* aff   = (float2*)p7;
    float*  fragS = (float*)p8;
    float*  fragD = (float*)p9;
    float*  bb    = (float*)pb;

    const int ESM  = 128 * 132 * 4;   // 67584
    const int NSM1 = 64 * 68 * 4;     // 17408
    cudaFuncSetAttribute(k_edge, cudaFuncAttributeMaxDynamicSharedMemorySize, ESM);
    cudaFuncSetAttribute(k_node, cudaFuncAttributeMaxDynamicSharedMemorySize, NSM1);

    // 0: init + fragment precompute + bias pack (one launch)
    k_initprep<<<4109, 256>>>(x, w_up, w_dn, w1, w2, wcomb, b_up, b_dn);

    // 1: boundary scatter
    k_boundary<<<16384, 256>>>(b_attr, b_idx, acc + 2 * ND, EB);

    // 2: P[z] = x @ W_top[z] + b[z], z in {up, dn}; fZ=32768 (skip Bot frags)
    k_node<<<dim3(512, 1, 2), 256, NSM1>>>(
        x, 0, 0, fragS, 32768, bb, 128, (const float2*)0, 0, xW, ND, 128);

    // 3: edge GEMM + scatter, up & dn merged
    k_edge<<<dim3(4096, 1, 2), 256, ESM>>>(up_attr, dn_attr,
                                           fragS + 16384, fragS + 49152,
                                           xW, up_idx, dn_idx, acc, EUP);

    // 4: z1 = h @ w1 + b1
    k_node<<<dim3(512, 1, 3), 256, NSM1>>>(
        acc, ND, 0, fragD, 16384, bb1, 128, (const float2*)0, 0, z1, ND, 128);
    k_stats<<<dim3(256, 1, 3), 128>>>(z1, ND, sums);
    k_fin<<<3, 128>>>(sums, g1, be1, aff, 384);

    // 5: z2 = relu(bn(z1)) @ w2 + b2
    k_node<<<dim3(512, 1, 3), 256, NSM1>>>(
        z1, ND, 0, fragD + 3 * 16384, 16384, bb2, 128, aff, 128, z2, ND, 128);
    k_stats<<<dim3(256, 1, 3), 128>>>(z2, ND, sums + 768);
    k_fin<<<3, 128>>>(sums + 768, g2, be2, aff + 384, 384);

    // 6: zc = cat(relu(bn(z2))) @ comb_w + comb_b (K=384, 3 frag segments)
    k_node<<<dim3(512, 1, 1), 256, NSM1>>>(
        z2, 0, ND, fragD + 6 * 16384, 0, bcomb, 0, aff + 384, 0, zc, 0, 384);
    k_stats<<<dim3(256, 1, 1), 128>>>(zc, 0, sums + 1536);
    k_fin<<<1, 128>>>(sums + 1536, gcomb, becomb, aff + 768, 128);

    // 7: out = relu(bn(zc))
    k_out<<<4096, 256>>>(out);
}